// round 16
// baseline (speedup 1.0000x reference)
#include <cuda_runtime.h>
#include <cuda_fp16.h>
#include <cstdint>

#define NN 50000
#define NE 800000
#define DH 128
#define DOUT 64
#define SLOT 96

// ---------------- device scratch (no allocations allowed) ----------------
__device__ int   g_cnt[NN];
__device__ int   g_col[NN * SLOT];
__device__ float g_W12[DH * DOUT];
__device__ float g_b12[DOUT];
__device__ int   g_is64;

// fp16 activation planes
__device__ __half g_x16[NN * DH];
__device__ __half g_a16[NN * DH];
__device__ __half g_h1_16[NN * DH];
__device__ __half g_h2_16[NN * DH];
// transposed, stacked, hi/lo-split weights: B[n][k], k = [Wl rows | Wr rows]
__device__ __half g_B0h[128 * 256], g_B0l[128 * 256];
__device__ __half g_B1h[128 * 256], g_B1l[128 * 256];
__device__ __half g_B2h[128 * 256], g_B2l[128 * 256];
__device__ __half g_B3h[64 * 128],  g_B3l[64 * 128];

// ---------------- fused: zero counters + dtype probe + W12 fold --------------
#define ZB 196  // ceil(NN/256)
__global__ void k_zero_w12(const int* __restrict__ ei32,
                           const float* __restrict__ W1, const float* __restrict__ W2,
                           const float* __restrict__ b1, const float* __restrict__ b2) {
    int b = blockIdx.x;
    if (b < ZB) {
        int i = b * 256 + threadIdx.x;
        if (i < NN) g_cnt[i] = 0;
        if (b == 0 && threadIdx.x == 0) {
            int odd_nonzero = 0;
            for (int j = 0; j < 64; j++)
                if (ei32[2 * j + 1] != 0) odd_nonzero++;
            g_is64 = (odd_nonzero == 0) ? 1 : 0;
        }
    } else {
        int idx = (b - ZB) * 256 + threadIdx.x;
        if (idx < DH * DOUT) {
            int i = idx / DOUT, j = idx % DOUT;
            float s = 0.f;
            for (int k = 0; k < DH; k++) s += W1[i * DH + k] * W2[k * DOUT + j];
            g_W12[idx] = s;
        }
        if (idx < DOUT) {
            float s = b2[idx];
            for (int k = 0; k < DH; k++) s += b1[k] * W2[k * DOUT + idx];
            g_b12[idx] = s;
        }
    }
}
#define ZW_BLOCKS (ZB + 32)

// ---------------- fused: edge append + x->fp16 + weight split ----------------
__device__ __forceinline__ void wseg(const float* __restrict__ Wa, const float* __restrict__ Wb,
                                     __half* __restrict__ oh, __half* __restrict__ ol,
                                     int blk, int N, int ktot) {
    int idx = blk * 256 + threadIdx.x;
    if (idx >= N * ktot) return;
    int n = idx / ktot, k = idx % ktot;
    float w = (k < 128) ? Wa[k * N + n] : Wb[(k - 128) * N + n];
    __half h = __float2half_rn(w);
    __half l = __float2half_rn(w - __half2float(h));
    oh[idx] = h; ol[idx] = l;
}

#define APP_BLOCKS 3125    // NE/256
#define CVT_BLOCKS 6250    // NN*DH/4/256
__global__ void k_appendprep(const int* __restrict__ ei32, const float* __restrict__ x,
                             const float* __restrict__ Wl0, const float* __restrict__ Wr0,
                             const float* __restrict__ Wl1, const float* __restrict__ Wr1,
                             const float* __restrict__ Wl2, const float* __restrict__ Wr2) {
    int b = blockIdx.x;
    if (b < APP_BLOCKS) {
        int e = b * 256 + threadIdx.x;
        if (e >= NE) return;
        int is64 = g_is64;
        int d = is64 ? ei32[2 * (NE + e)] : ei32[NE + e];
        int s = is64 ? ei32[2 * e] : ei32[e];
        if (d >= 0 && d < NN && s >= 0 && s < NN) {
            int p = atomicAdd(&g_cnt[d], 1);
            if (p < SLOT) g_col[d * SLOT + p] = s;
        }
    } else if (b < APP_BLOCKS + CVT_BLOCKS) {
        int idx = (b - APP_BLOCKS) * 256 + threadIdx.x;  // group of 4 floats
        float4 v = *(const float4*)(x + idx * 4);
        __half2 p01 = __floats2half2_rn(v.x, v.y);
        __half2 p23 = __floats2half2_rn(v.z, v.w);
        uint2 u;
        u.x = *(uint32_t*)&p01; u.y = *(uint32_t*)&p23;
        *(uint2*)(g_x16 + idx * 4) = u;
    } else if (b < APP_BLOCKS + CVT_BLOCKS + 128) {
        wseg(Wl0, Wr0, g_B0h, g_B0l, b - (APP_BLOCKS + CVT_BLOCKS), 128, 256);
    } else if (b < APP_BLOCKS + CVT_BLOCKS + 256) {
        wseg(Wl1, Wr1, g_B1h, g_B1l, b - (APP_BLOCKS + CVT_BLOCKS + 128), 128, 256);
    } else if (b < APP_BLOCKS + CVT_BLOCKS + 384) {
        wseg(Wl2, Wr2, g_B2h, g_B2l, b - (APP_BLOCKS + CVT_BLOCKS + 256), 128, 256);
    } else {
        wseg(g_W12, nullptr, g_B3h, g_B3l, b - (APP_BLOCKS + CVT_BLOCKS + 384), 64, 128);
    }
}
#define AP_BLOCKS (APP_BLOCKS + CVT_BLOCKS + 384 + 32)

// ---------------- mean aggregation: half-warp per node, uint4 loads ----------
__device__ __forceinline__ void hacc(float* a, uint4 p) {
    __half2* hp = (__half2*)&p;
#pragma unroll
    for (int j = 0; j < 4; j++) {
        float2 f = __half22float2(hp[j]);
        a[2 * j] += f.x; a[2 * j + 1] += f.y;
    }
}

__global__ void k_agg16(const __half* __restrict__ I, __half* __restrict__ O) {
    int hw = (blockIdx.x * blockDim.x + threadIdx.x) >> 4;  // node id
    int lane = threadIdx.x & 15;
    if (hw >= NN) return;
    int cnt = g_cnt[hw];
    if (cnt > SLOT) cnt = SLOT;
    const int* cl = g_col + hw * SLOT;
    float a[8] = {0.f, 0.f, 0.f, 0.f, 0.f, 0.f, 0.f, 0.f};
    int e = 0;
    for (; e + 1 < cnt; e += 2) {
        int s0 = cl[e], s1 = cl[e + 1];
        uint4 p0 = __ldg((const uint4*)(I + (size_t)s0 * DH + lane * 8));
        uint4 p1 = __ldg((const uint4*)(I + (size_t)s1 * DH + lane * 8));
        hacc(a, p0); hacc(a, p1);
    }
    if (e < cnt) {
        int s0 = cl[e];
        hacc(a, __ldg((const uint4*)(I + (size_t)s0 * DH + lane * 8)));
    }
    float inv = 1.0f / fmaxf((float)cnt, 1.0f);
    __half2 o[4];
#pragma unroll
    for (int j = 0; j < 4; j++)
        o[j] = __floats2half2_rn(a[2 * j] * inv, a[2 * j + 1] * inv);
    uint4 u;
    u.x = *(uint32_t*)&o[0]; u.y = *(uint32_t*)&o[1];
    u.z = *(uint32_t*)&o[2]; u.w = *(uint32_t*)&o[3];
    *(uint4*)(O + (size_t)hw * DH + lane * 8) = u;
}

// ---------------- tensor-core GEMM: cp.async 2-stage pipeline ----------------
__device__ __forceinline__ void ldx4(uint32_t r[4], const __half* p) {
    uint32_t a = (uint32_t)__cvta_generic_to_shared(p);
    asm volatile("ldmatrix.sync.aligned.m8n8.x4.shared.b16 {%0,%1,%2,%3}, [%4];"
                 : "=r"(r[0]), "=r"(r[1]), "=r"(r[2]), "=r"(r[3]) : "r"(a));
}

__device__ __forceinline__ void mma_f16(float c[4], const uint32_t a[4], const uint32_t b[2]) {
    asm volatile(
        "mma.sync.aligned.m16n8k16.row.col.f32.f16.f16.f32 "
        "{%0,%1,%2,%3},{%4,%5,%6,%7},{%8,%9},{%0,%1,%2,%3};"
        : "+f"(c[0]), "+f"(c[1]), "+f"(c[2]), "+f"(c[3])
        : "r"(a[0]), "r"(a[1]), "r"(a[2]), "r"(a[3]), "r"(b[0]), "r"(b[1]));
}

__device__ __forceinline__ void cpa16(uint32_t dst, const void* src, bool v) {
    int sz = v ? 16 : 0;
    asm volatile("cp.async.cg.shared.global [%0], [%1], 16, %2;"
                 :: "r"(dst), "l"(src), "r"(sz) : "memory");
}
#define CP_COMMIT() asm volatile("cp.async.commit_group;" ::: "memory")
#define CP_WAIT1()  asm volatile("cp.async.wait_group 1;" ::: "memory")

// C = act([A1|A2] @ B^T + bias); A fp16 [M][128]; B planes [BN][KT] (n-major).
// 128 rows x BN cols per CTA, 256 threads, 8 warps (4 M x 2 N), double-buffered.
// B fragments loaded and consumed immediately to keep live registers low
// (target 3 CTAs/SM -> single wave at grid=391).
template <int BN, bool DUAL, bool RELU, bool F32OUT>
__launch_bounds__(256, 3)
__global__ void k_mma(const __half* __restrict__ A1, const __half* __restrict__ A2,
                      const __half* __restrict__ Bh, const __half* __restrict__ Bl,
                      const float* __restrict__ bias,
                      float* __restrict__ Cf, __half* __restrict__ C16) {
    constexpr int KT  = DUAL ? 256 : 128;
    constexpr int NCH = KT / 32;
    constexpr int AS  = 40;                 // smem row stride in halves (80B)
    constexpr int ABYTES = 128 * AS * 2;    // 10240
    constexpr int BBYTES = BN * AS * 2;
    constexpr int WN = BN / 2;
    constexpr int NF = WN / 8;
    constexpr int NG = WN / 16;

    extern __shared__ __align__(16) char smem[];
    uint32_t sb = (uint32_t)__cvta_generic_to_shared(smem);

    int t = threadIdx.x, lane = t & 31, warp = t >> 5;
    int wm = warp >> 1, wn = warp & 1;
    int m0 = wm * 32, n0w = wn * WN;
    int gr0 = blockIdx.x * 128;

    float acc[2][NF][4];
#pragma unroll
    for (int fm = 0; fm < 2; fm++)
#pragma unroll
        for (int fn = 0; fn < NF; fn++)
#pragma unroll
            for (int j = 0; j < 4; j++) acc[fm][fn][j] = 0.f;

    int arow = lane & 15;
    int ako  = (lane >> 4) << 3;
    int brow = (lane & 7) + ((lane >> 4) << 3);
    int bko  = (lane & 8) ? 8 : 0;

    auto stage = [&](int ch, int b) {
        const __half* A = (DUAL && ch >= 4) ? A2 : A1;
        int kb = (ch * 32) & 127;
        int k0 = ch * 32;
        uint32_t sAb  = sb + b * ABYTES;
        uint32_t sBhb = sb + 2 * ABYTES + b * BBYTES;
        uint32_t sBlb = sb + 2 * ABYTES + 2 * BBYTES + b * BBYTES;
#pragma unroll
        for (int i = 0; i < 2; i++) {
            int c = t + i * 256;
            int row = c >> 2, c4 = c & 3;
            int gr = gr0 + row;
            cpa16(sAb + (row * AS + c4 * 8) * 2,
                  A + (size_t)gr * 128 + kb + c4 * 8, gr < NN);
        }
#pragma unroll
        for (int i = 0; i < (BN * 4) / 256; i++) {
            int c = t + i * 256;
            int row = c >> 2, c4 = c & 3;
            cpa16(sBhb + (row * AS + c4 * 8) * 2,
                  Bh + (size_t)row * KT + k0 + c4 * 8, true);
            cpa16(sBlb + (row * AS + c4 * 8) * 2,
                  Bl + (size_t)row * KT + k0 + c4 * 8, true);
        }
    };

    stage(0, 0);
    CP_COMMIT();

    for (int ch = 0; ch < NCH; ch++) {
        if (ch + 1 < NCH) stage(ch + 1, (ch + 1) & 1);
        CP_COMMIT();
        CP_WAIT1();
        __syncthreads();

        const __half* sA  = (const __half*)(smem + (ch & 1) * ABYTES);
        const __half* sBh = (const __half*)(smem + 2 * ABYTES + (ch & 1) * BBYTES);
        const __half* sBl = (const __half*)(smem + 2 * ABYTES + 2 * BBYTES + (ch & 1) * BBYTES);

#pragma unroll
        for (int kk = 0; kk < 32; kk += 16) {
            uint32_t a[2][4];
#pragma unroll
            for (int fm = 0; fm < 2; fm++)
                ldx4(a[fm], sA + (m0 + fm * 16 + arow) * AS + kk + ako);
#pragma unroll
            for (int g = 0; g < NG; g++) {
                uint32_t rh[4], rl[4];
                ldx4(rh, sBh + (n0w + g * 16 + brow) * AS + kk + bko);
                ldx4(rl, sBl + (n0w + g * 16 + brow) * AS + kk + bko);
                // per accumulator: hi term then lo term (order preserved)
#pragma unroll
                for (int fm = 0; fm < 2; fm++) {
                    mma_f16(acc[fm][2 * g],     a[fm], rh);
                    mma_f16(acc[fm][2 * g],     a[fm], rl);
                    mma_f16(acc[fm][2 * g + 1], a[fm], rh + 2);
                    mma_f16(acc[fm][2 * g + 1], a[fm], rl + 2);
                }
            }
        }
        __syncthreads();
    }

    // epilogue
    int r4 = lane >> 2, cpair = (lane & 3) * 2;
#pragma unroll
    for (int fm = 0; fm < 2; fm++)
#pragma unroll
        for (int fn = 0; fn < NF; fn++) {
            int col = n0w + fn * 8 + cpair;
            float bb0 = __ldg(bias + col), bb1 = __ldg(bias + col + 1);
            int r0 = gr0 + m0 + fm * 16 + r4;
            int r1 = r0 + 8;
            float v00 = acc[fm][fn][0] + bb0, v01 = acc[fm][fn][1] + bb1;
            float v10 = acc[fm][fn][2] + bb0, v11 = acc[fm][fn][3] + bb1;
            if (RELU) {
                v00 = fmaxf(v00, 0.f); v01 = fmaxf(v01, 0.f);
                v10 = fmaxf(v10, 0.f); v11 = fmaxf(v11, 0.f);
            }
            if (F32OUT) {
                if (r0 < NN) { float2 o = {v00, v01}; *(float2*)(Cf + (size_t)r0 * BN + col) = o; }
                if (r1 < NN) { float2 o = {v10, v11}; *(float2*)(Cf + (size_t)r1 * BN + col) = o; }
            } else {
                if (r0 < NN) *(__half2*)(C16 + (size_t)r0 * 128 + col) = __floats2half2_rn(v00, v01);
                if (r1 < NN) *(__half2*)(C16 + (size_t)r1 * 128 + col) = __floats2half2_rn(v10, v11);
            }
        }
}

#define MMA_SMEM_128 (2 * 10240 + 4 * 128 * 40 * 2)  // 61440
#define MMA_SMEM_64  (2 * 10240 + 4 * 64 * 40 * 2)   // 40960

// ---------------- launch ----------------
extern "C" void kernel_launch(void* const* d_in, const int* in_sizes, int n_in,
                              void* d_out, int out_size) {
    const float* x    = (const float*)d_in[0];
    const int*   ei32 = (const int*)d_in[1];
    const float* Wl0 = (const float*)d_in[2];
    const float* bl0 = (const float*)d_in[3];
    const float* Wr0 = (const float*)d_in[4];
    const float* Wl1 = (const float*)d_in[5];
    const float* bl1 = (const float*)d_in[6];
    const float* Wr1 = (const float*)d_in[7];
    const float* Wl2 = (const float*)d_in[8];
    const float* bl2 = (const float*)d_in[9];
    const float* Wr2 = (const float*)d_in[10];
    const float* W1  = (const float*)d_in[11];
    const float* b1  = (const float*)d_in[12];
    const float* W2  = (const float*)d_in[13];
    const float* b2  = (const float*)d_in[14];
    float* out = (float*)d_out;

    __half *x16, *a16, *h1, *h2;
    __half *B0h, *B0l, *B1h, *B1l, *B2h, *B2l, *B3h, *B3l;
    float *b12;
    cudaGetSymbolAddress((void**)&x16, g_x16);
    cudaGetSymbolAddress((void**)&a16, g_a16);
    cudaGetSymbolAddress((void**)&h1, g_h1_16);
    cudaGetSymbolAddress((void**)&h2, g_h2_16);
    cudaGetSymbolAddress((void**)&B0h, g_B0h); cudaGetSymbolAddress((void**)&B0l, g_B0l);
    cudaGetSymbolAddress((void**)&B1h, g_B1h); cudaGetSymbolAddress((void**)&B1l, g_B1l);
    cudaGetSymbolAddress((void**)&B2h, g_B2h); cudaGetSymbolAddress((void**)&B2l, g_B2l);
    cudaGetSymbolAddress((void**)&B3h, g_B3h); cudaGetSymbolAddress((void**)&B3l, g_B3l);
    cudaGetSymbolAddress((void**)&b12, g_b12);

    cudaFuncSetAttribute(k_mma<128, true, true, false>,
                         cudaFuncAttributeMaxDynamicSharedMemorySize, MMA_SMEM_128);
    cudaFuncSetAttribute(k_mma<64, false, false, true>,
                         cudaFuncAttributeMaxDynamicSharedMemorySize, MMA_SMEM_64);

    // adjacency build + prep (9 launches total)
    k_zero_w12<<<ZW_BLOCKS, 256>>>(ei32, W1, W2, b1, b2);
    k_appendprep<<<AP_BLOCKS, 256>>>(ei32, x, Wl0, Wr0, Wl1, Wr1, Wl2, Wr2);

    const int aggBlocks = (NN * 16 + 255) / 256;
    const int mmaBlocks = (NN + 127) / 128;

    // layer 0
    k_agg16<<<aggBlocks, 256>>>(x16, a16);
    k_mma<128, true, true, false><<<mmaBlocks, 256, MMA_SMEM_128>>>(a16, x16, B0h, B0l, bl0, nullptr, h1);
    // layer 1
    k_agg16<<<aggBlocks, 256>>>(h1, a16);
    k_mma<128, true, true, false><<<mmaBlocks, 256, MMA_SMEM_128>>>(a16, h1, B1h, B1l, bl1, nullptr, h2);
    // layer 2
    k_agg16<<<aggBlocks, 256>>>(h2, a16);
    k_mma<128, true, true, false><<<mmaBlocks, 256, MMA_SMEM_128>>>(a16, h2, B2h, B2l, bl2, nullptr, h1);
    // post MLP (folded, fp32 out)
    k_mma<64, false, false, true><<<mmaBlocks, 256, MMA_SMEM_64>>>(h1, nullptr, B3h, B3l, b12, out, nullptr);
}